// round 1
// baseline (speedup 1.0000x reference)
#include <cuda_runtime.h>

// EnergyModel: energy[t] = sum_q qa[q] * sum_f w[f]*(desc[t,q,f]-qf[t,q,f])^2
// with range masking on T[:,4:7]. HBM-bound streaming reduction.

#define NQ 128
#define FDIM 576          // 64*1 + 64*3 + 64*5
#define NGRP 192
#define THREADS 512
#define F4_PER_ROW (FDIM / 4)          // 144
#define F4_TOTAL (NQ * F4_PER_ROW)     // 18432 float4 per t per tensor

__global__ void __launch_bounds__(THREADS)
energy_kernel(const float* __restrict__ T,
              const float4* __restrict__ desc,
              const float4* __restrict__ qf,
              const float* __restrict__ qa,
              const float* __restrict__ logit,
              const float* __restrict__ ranges,
              float* __restrict__ out)
{
    const int t   = blockIdx.x;
    const int tid = threadIdx.x;

    __shared__ float s_w[FDIM];
    __shared__ float s_qa[NQ];
    __shared__ float s_red[THREADS / 32];
    __shared__ int   s_mask;

    // Range mask check first: masked rows never touch the 590KB payload.
    if (tid == 0) {
        float x0 = T[t * 7 + 4];
        float x1 = T[t * 7 + 5];
        float x2 = T[t * 7 + 6];
        bool ok = (ranges[1] >= x0) && (x0 >= ranges[0]) &&
                  (ranges[3] >= x1) && (x1 >= ranges[2]) &&
                  (ranges[5] >= x2) && (x2 >= ranges[4]);
        s_mask = ok ? 0 : 1;
    }
    __syncthreads();
    if (s_mask) {
        if (tid == 0) out[t] = 100000.0f;
        return;
    }

    // Stage per-feature weights (expand per-copy softplus weight to features)
    // and per-query attention into shared.
    const float inv = 1.0f / (0.6931471805599453f * (float)NGRP);
    for (int f = tid; f < FDIM; f += THREADS) {
        int c;
        if (f < 64)        c = f;                       // l=0, d=1
        else if (f < 256)  c = 64 + (f - 64) / 3;       // l=1, d=3
        else               c = 128 + (f - 256) / 5;     // l=2, d=5
        float x  = logit[c];
        float sp = fmaxf(x, 0.0f) + log1pf(expf(-fabsf(x)));  // stable softplus
        s_w[f] = 2.0f * sp * inv;
    }
    for (int q = tid; q < NQ; q += THREADS) s_qa[q] = qa[q];
    __syncthreads();

    const float4* dbase = desc + (size_t)t * F4_TOTAL;
    const float4* qbase = qf   + (size_t)t * F4_TOTAL;

    float acc = 0.0f;
    #pragma unroll 4
    for (int j = tid; j < F4_TOTAL; j += THREADS) {
        int q = j / F4_PER_ROW;
        int f = (j - q * F4_PER_ROW) * 4;
        float4 d = dbase[j];
        float4 e = qbase[j];
        float dx = d.x - e.x;
        float dy = d.y - e.y;
        float dz = d.z - e.z;
        float dw = d.w - e.w;
        float s = s_w[f] * dx * dx;
        s = fmaf(s_w[f + 1], dy * dy, s);
        s = fmaf(s_w[f + 2], dz * dz, s);
        s = fmaf(s_w[f + 3], dw * dw, s);
        acc = fmaf(s_qa[q], s, acc);
    }

    // Block reduction: warp shuffle, then first warp folds the 16 partials.
    #pragma unroll
    for (int o = 16; o > 0; o >>= 1)
        acc += __shfl_down_sync(0xffffffffu, acc, o);
    if ((tid & 31) == 0) s_red[tid >> 5] = acc;
    __syncthreads();
    if (tid < 32) {
        float v = (tid < THREADS / 32) ? s_red[tid] : 0.0f;
        #pragma unroll
        for (int o = 8; o > 0; o >>= 1)
            v += __shfl_down_sync(0xffffffffu, v, o);
        if (tid == 0) out[t] = v;
    }
}

extern "C" void kernel_launch(void* const* d_in, const int* in_sizes, int n_in,
                              void* d_out, int out_size)
{
    const float*  T      = (const float*)d_in[0];
    const float4* desc   = (const float4*)d_in[1];
    const float4* qf     = (const float4*)d_in[2];
    const float*  qa     = (const float*)d_in[3];
    const float*  logit  = (const float*)d_in[4];
    const float*  ranges = (const float*)d_in[5];
    float* out = (float*)d_out;

    const int nt = in_sizes[0] / 7;   // 1024

    energy_kernel<<<nt, THREADS>>>(T, desc, qf, qa, logit, ranges, out);
}